// round 13
// baseline (speedup 1.0000x reference)
#include <cuda_runtime.h>
#include <cstdint>

#define BB   16
#define N1   4096
#define N2   1024
#define C2   256
#define OUTC 256
#define KG   4096
#define NNZ  (N1 * 3)

// ---------------- scratch ------------------------------------------------------
__device__ float4         g_wi[BB * N1];
__device__ int            g_histq[BB][4][N2];
__device__ int            g_off[BB * N2];
__device__ int            g_end[BB * N2];
__device__ float2         g_le[BB * NNZ];
__device__ float          g_W1T[(size_t)KG * OUTC];
__device__ float          g_T[(size_t)BB * N2 * OUTC];
__device__ unsigned short g_APh[(size_t)BB * C2 * N2];
__device__ unsigned short g_APl[(size_t)BB * C2 * N2];
__device__ unsigned short g_BPh[(size_t)BB * OUTC * N2];
__device__ unsigned short g_BPl[(size_t)BB * OUTC * N2];
__device__ float          g_y[BB * C2 * OUTC];
__device__ float          g_y2[BB * C2 * OUTC];
__device__ float          g_ysum[BB * C2 * OUTC];
__device__ float          g_mean[C2];
__device__ float          g_rstd[C2];
__device__ int            g_ctr;

__device__ __forceinline__ uint32_t smem_u32(const void* p) {
    uint32_t a;
    asm("{ .reg .u64 t; cvta.to.shared.u64 t, %1; cvt.u32.u64 %0, t; }" : "=r"(a) : "l"(p));
    return a;
}
__device__ __forceinline__ void split2(float f0, float f1, uint32_t& h, uint32_t& l) {
    asm("cvt.rn.bf16x2.f32 %0, %1, %2;" : "=r"(h) : "f"(f1), "f"(f0));
    float fh0 = __int_as_float(h << 16);
    float fh1 = __int_as_float(h & 0xffff0000u);
    asm("cvt.rn.bf16x2.f32 %0, %1, %2;" : "=r"(l) : "f"(f1 - fh1), "f"(f0 - fh0));
}
__device__ __forceinline__ void fma2(unsigned long long& d, unsigned long long a,
                                     unsigned long long b) {
    asm("fma.rn.f32x2 %0, %1, %2, %0;" : "+l"(d) : "l"(a), "l"(b));
}

// ---------------- mega0: knn+hist | W1->W1T | x2 pack -----------------------------
// blocks [0,64): knn (b = blk>>2, quarter = blk&3, 1024 threads = 1024 n's)
// blocks [64,320): W1 transpose    [320,1344): x2 transpose+split pack
__global__ __launch_bounds__(1024) void mega0_kernel(const float* __restrict__ W1,
                                                     const float* __restrict__ x2,
                                                     const float* __restrict__ xyz1,
                                                     const float* __restrict__ xyz2) {
    __shared__ __align__(16) char smem[20480];
    const int t = threadIdx.x;

    if (blockIdx.x < 64) {
        float4* qA = (float4*)smem;          // 512 pairs: (x0,x1,y0,y1)
        float4* qB = qA + 512;               // (z0,z1,w0,w1)
        int* hist = (int*)(smem + 16384);
        const int b = blockIdx.x >> 2, qq = blockIdx.x & 3;
        {
            const float* x2b = xyz2 + (size_t)b * N2 * 3;
            float x = x2b[t * 3 + 0], y = x2b[t * 3 + 1], z = x2b[t * 3 + 2];
            int pr = t >> 1, hi = t & 1;
            ((float*)&qA[pr])[hi]     = x;
            ((float*)&qA[pr])[2 + hi] = y;
            ((float*)&qB[pr])[hi]     = z;
            ((float*)&qB[pr])[2 + hi] = x * x + y * y + z * z;
            hist[t] = 0;
        }
        __syncthreads();

        const int n = qq * 1024 + t;
        const float* p = xyz1 + ((size_t)b * N1 + n) * 3;
        const float px = p[0], py = p[1], pz = p[2];
        const float pp = px * px + py * py + pz * pz;
        unsigned long long ax2, ay2, az2;
        {
            float ax = -2.f * px, ay = -2.f * py, az = -2.f * pz;
            asm("mov.b64 %0, {%1,%1};" : "=l"(ax2) : "f"(ax));
            asm("mov.b64 %0, {%1,%1};" : "=l"(ay2) : "f"(ay));
            asm("mov.b64 %0, {%1,%1};" : "=l"(az2) : "f"(az));
        }
        const float INF = __int_as_float(0x7f800000);
        float s0 = INF, s1 = INF, s2 = INF;
        int i0 = 0, i1 = 0, i2 = 0;
#pragma unroll 4
        for (int q = 0; q < 512; ++q) {
            ulonglong2 A = *(const ulonglong2*)(qA + q);
            ulonglong2 B = *(const ulonglong2*)(qB + q);
            unsigned long long acc = B.y;
            fma2(acc, ax2, A.x);
            fma2(acc, ay2, A.y);
            fma2(acc, az2, B.x);
            float slo, shi;
            asm("mov.b64 {%0,%1}, %2;" : "=f"(slo), "=f"(shi) : "l"(acc));
#pragma unroll
            for (int h = 0; h < 2; ++h) {
                float s = h ? shi : slo;
                int j = 2 * q + h;
                if (s < s2) {
                    if (s < s1) {
                        s2 = s1; i2 = i1;
                        if (s < s0) { s1 = s0; i1 = i0; s0 = s; i0 = j; }
                        else        { s1 = s;  i1 = j; }
                    } else { s2 = s; i2 = j; }
                }
            }
        }
        float d0 = s0 + pp, d1 = s1 + pp, d2 = s2 + pp;
        float r0 = 1.f / (d0 + 1e-8f), r1 = 1.f / (d1 + 1e-8f), r2 = 1.f / (d2 + 1e-8f);
        float rs = 1.f / (r0 + r1 + r2);
        int packed = i0 | (i1 << 10) | (i2 << 20);
        g_wi[b * N1 + n] = make_float4(r0 * rs, r1 * rs, r2 * rs, __int_as_float(packed));
        atomicAdd(&hist[i0], 1);
        atomicAdd(&hist[i1], 1);
        atomicAdd(&hist[i2], 1);
        __syncthreads();
        g_histq[b][qq][t] = hist[t];
    } else if (blockIdx.x < 320) {
        float (*tile)[65] = (float (*)[65])smem;
        const int tt = blockIdx.x - 64;
        const int n0 = (tt & 63) * 64, o0 = (tt >> 6) * 64;
        const int tx = t & 63, ty = t >> 6;
#pragma unroll
        for (int i = 0; i < 4; ++i)
            tile[ty + 16 * i][tx] = W1[(size_t)(o0 + ty + 16 * i) * KG + n0 + tx];
        __syncthreads();
#pragma unroll
        for (int i = 0; i < 4; ++i)
            g_W1T[(size_t)(n0 + ty + 16 * i) * OUTC + o0 + tx] = tile[tx][ty + 16 * i];
    } else {
        float (*tile)[65] = (float (*)[65])smem;
        const int tt = blockIdx.x - 320;
        const int b = tt >> 6;
        const int ti = tt & 63;
        const int k0 = (ti >> 2) * 64, c0 = (ti & 3) * 64;
        const int kr = t >> 4, c4 = (t & 15) * 4;
        float4 f4 = *(const float4*)(x2 + ((size_t)(b * N2 + k0 + kr)) * 256 + c0 + c4);
        tile[kr][c4 + 0] = f4.x; tile[kr][c4 + 1] = f4.y;
        tile[kr][c4 + 2] = f4.z; tile[kr][c4 + 3] = f4.w;
        __syncthreads();
        const int cr = t >> 4, k4 = (t & 15) * 4;
        float g0 = tile[k4 + 0][cr], g1 = tile[k4 + 1][cr];
        float g2 = tile[k4 + 2][cr], g3 = tile[k4 + 3][cr];
        uint32_t h01, l01, h23, l23;
        split2(g0, g1, h01, l01);
        split2(g2, g3, h23, l23);
        const size_t doff = ((size_t)(b * 256 + c0 + cr) << 10) + k0 + k4;
        *(uint2*)(g_APh + doff) = make_uint2(h01, h23);
        *(uint2*)(g_APl + doff) = make_uint2(l01, l23);
    }
}

// ---------------- fillk: per-quarter scan + CSC fill (128 blocks) -----------------
__global__ __launch_bounds__(1024) void fillk_kernel() {
    __shared__ int cur[N2];
    __shared__ int wpart[32];
    const int b = blockIdx.y, qq = blockIdx.x, t = threadIdx.x;
    const int m = t;
    const int h0 = g_histq[b][0][m], h1 = g_histq[b][1][m];
    const int h2 = g_histq[b][2][m], h3 = g_histq[b][3][m];
    const int cnt = h0 + h1 + h2 + h3;
    int before = 0;
    if (qq > 0) before += h0;
    if (qq > 1) before += h1;
    if (qq > 2) before += h2;

    const int lane = t & 31, wid = t >> 5;
    int v = cnt;
#pragma unroll
    for (int d = 1; d < 32; d <<= 1) {
        int u = __shfl_up_sync(0xffffffffu, v, d);
        if (lane >= d) v += u;
    }
    if (lane == 31) wpart[wid] = v;
    __syncthreads();
    if (wid == 0) {
        int w = wpart[lane];
#pragma unroll
        for (int d = 1; d < 32; d <<= 1) {
            int u = __shfl_up_sync(0xffffffffu, w, d);
            if (lane >= d) w += u;
        }
        wpart[lane] = w;
    }
    __syncthreads();
    const int excl = v - cnt + (wid > 0 ? wpart[wid - 1] : 0);
    if (qq == 0) {
        g_off[b * N2 + m] = excl;
        g_end[b * N2 + m] = excl + cnt;
    }
    cur[m] = excl + before;
    __syncthreads();

    const int n = qq * 1024 + t;
    float4 wi = g_wi[b * N1 + n];
    int p = __float_as_int(wi.w);
    float fn = __int_as_float(n);
    const int lbase = b * NNZ;
    int p0 = atomicAdd(&cur[p & 1023], 1);
    g_le[lbase + p0] = make_float2(wi.x, fn);
    int p1 = atomicAdd(&cur[(p >> 10) & 1023], 1);
    g_le[lbase + p1] = make_float2(wi.y, fn);
    int p2 = atomicAdd(&cur[(p >> 20) & 1023], 1);
    g_le[lbase + p2] = make_float2(wi.z, fn);
}

// ---------------- tbuild: T[b,m,o] (measured 18.6us, L2 roofline) -----------------
__global__ __launch_bounds__(256) void tbuild_kernel() {
    const int b = blockIdx.y;
    const int m = blockIdx.x * 4 + (threadIdx.x >> 6);
    const int o4 = (threadIdx.x & 63) << 2;
    const int lbase = b * NNZ;
    const int s0 = __ldg(&g_off[b * N2 + m]);
    const int s1 = __ldg(&g_end[b * N2 + m]);

    float4 acc = make_float4(0.f, 0.f, 0.f, 0.f);
    int i = s0;
    for (; i + 2 <= s1; i += 2) {
        float2 e0 = __ldg(&g_le[lbase + i]);
        float2 e1 = __ldg(&g_le[lbase + i + 1]);
        int n0 = __float_as_int(e0.y), n1 = __float_as_int(e1.y);
        float4 v0 = *(const float4*)(g_W1T + ((size_t)n0 << 8) + o4);
        float4 v1 = *(const float4*)(g_W1T + ((size_t)n1 << 8) + o4);
        acc.x = fmaf(e0.x, v0.x, acc.x); acc.y = fmaf(e0.x, v0.y, acc.y);
        acc.z = fmaf(e0.x, v0.z, acc.z); acc.w = fmaf(e0.x, v0.w, acc.w);
        acc.x = fmaf(e1.x, v1.x, acc.x); acc.y = fmaf(e1.x, v1.y, acc.y);
        acc.z = fmaf(e1.x, v1.z, acc.z); acc.w = fmaf(e1.x, v1.w, acc.w);
    }
    if (i < s1) {
        float2 e = __ldg(&g_le[lbase + i]);
        int n = __float_as_int(e.y);
        float4 v = *(const float4*)(g_W1T + ((size_t)n << 8) + o4);
        acc.x = fmaf(e.x, v.x, acc.x); acc.y = fmaf(e.x, v.y, acc.y);
        acc.z = fmaf(e.x, v.z, acc.z); acc.w = fmaf(e.x, v.w, acc.w);
    }
    *(float4*)(g_T + ((size_t)b * N2 + m) * OUTC + o4) = acc;
}

// ---------------- bpack (PROFILED): T -> B planes ---------------------------------
__global__ void bpack_kernel() {
    __shared__ float tile[32][33];
    const int b = blockIdx.z;
    const int m0 = blockIdx.x * 32, o0 = blockIdx.y * 32;
    const int tx = threadIdx.x, ty = threadIdx.y;
#pragma unroll
    for (int i = 0; i < 4; ++i)
        tile[ty + 8 * i][tx] = g_T[((size_t)(b * N2 + m0 + ty + 8 * i)) * 256 + o0 + tx];
    __syncthreads();
#pragma unroll
    for (int i = 0; i < 4; ++i) {
        const int o = o0 + ty + 8 * i;
        const int m = m0 + tx;
        float f = tile[tx][ty + 8 * i];
        uint32_t h, l;
        split2(f, f, h, l);
        const size_t idx = ((size_t)(b * 256 + o) << 10) + m;
        g_BPh[idx] = (unsigned short)(h & 0xffffu);
        g_BPl[idx] = (unsigned short)(l & 0xffffu);
    }
}

// ---------------- GEMM: cp.async 4-stage, one sync/iter, split-K=2 ----------------
#define GTILE 8192
#define NST   16

#define MMA_BF16(d, A0, A1, A2, A3, B0, B1)                                     \
    asm volatile("mma.sync.aligned.m16n8k16.row.col.f32.bf16.bf16.f32 "         \
        "{%0,%1,%2,%3}, {%4,%5,%6,%7}, {%8,%9}, {%0,%1,%2,%3};"                 \
        : "+f"((d)[0]), "+f"((d)[1]), "+f"((d)[2]), "+f"((d)[3])                \
        : "r"(A0), "r"(A1), "r"(A2), "r"(A3), "r"(B0), "r"(B1))

#define LDSM4(r0, r1, r2, r3, a)                                                \
    asm volatile("ldmatrix.sync.aligned.m8n8.x4.shared.b16 {%0,%1,%2,%3}, [%4];" \
        : "=r"(r0), "=r"(r1), "=r"(r2), "=r"(r3) : "r"(a))

#define LDSM2(r0, r1, a)                                                        \
    asm volatile("ldmatrix.sync.aligned.m8n8.x2.shared.b16 {%0,%1}, [%2];"      \
        : "=r"(r0), "=r"(r1) : "r"(a))

#define CP_ASYNC(dst, src)                                                      \
    asm volatile("cp.async.cg.shared.global [%0], [%1], 16;"                    \
        :: "r"(dst), "l"(src) : "memory")
#define CP_COMMIT() asm volatile("cp.async.commit_group;" ::: "memory")
#define CP_WAIT2()  asm volatile("cp.async.wait_group 2;" ::: "memory")

__device__ __forceinline__ uint32_t swz(int r, int s, int h) {
    return (uint32_t)(r * 64 + ((s ^ ((r >> 1) & 1)) << 5) + ((h ^ ((r >> 2) & 1)) << 4));
}

__global__ __launch_bounds__(256, 1) void gemm_mma_kernel(const float* __restrict__ b1) {
    extern __shared__ __align__(128) char dyn[];
    const uint32_t sb = smem_u32(dyn);

    if (threadIdx.x == 0) g_ctr = 0;   // deterministic reset for statsepi barrier

    const int b  = blockIdx.y;
    const int c0 = (blockIdx.x & 1) * 128;
    const int o0 = ((blockIdx.x >> 1) & 1) * 128;
    const int z  = blockIdx.x >> 2;
    const int kbase = z * 512;

    const int tid  = threadIdx.x;
    const int lane = tid & 31;
    const int wid  = tid >> 5;
    const int wm   = wid & 1;
    const int wn   = wid >> 1;
    const int g    = lane >> 2;
    const int tq   = lane & 3;

    const unsigned short* srcs[4] = {
        g_APh + ((size_t)(b * 256 + c0) << 10),
        g_APl + ((size_t)(b * 256 + c0) << 10),
        g_BPh + ((size_t)(b * 256 + o0) << 10),
        g_BPl + ((size_t)(b * 256 + o0) << 10)
    };

    float acc[4][4][4];
#pragma unroll
    for (int mi = 0; mi < 4; ++mi)
#pragma unroll
        for (int ni = 0; ni < 4; ++ni)
#pragma unroll
            for (int r = 0; r < 4; ++r) acc[mi][ni][r] = 0.f;

    auto ldgsts = [&](int ks, int buf) {
        const int kg = kbase + ks * 32;
#pragma unroll
        for (int tile = 0; tile < 4; ++tile) {
            const uint32_t tb = sb + (uint32_t)(buf * 4 + tile) * GTILE;
#pragma unroll
            for (int it = 0; it < 2; ++it) {
                const int cid = it * 256 + tid;
                const int r = cid >> 2, ch = cid & 3;
                const unsigned short* gp = srcs[tile] + ((size_t)r << 10) + kg + ch * 8;
                CP_ASYNC(tb + swz(r, ch >> 1, ch & 1), gp);
            }
        }
    };

    auto compute16 = [&](int buf, int s) {
        const uint32_t ah_t = sb + (uint32_t)(buf * 4 + 0) * GTILE;
        const uint32_t al_t = sb + (uint32_t)(buf * 4 + 1) * GTILE;
        const uint32_t bh_t = sb + (uint32_t)(buf * 4 + 2) * GTILE;
        const uint32_t bl_t = sb + (uint32_t)(buf * 4 + 3) * GTILE;
        const int arow = wm * 64 + (lane & 15);
        const int ah = lane >> 4;
        const int brow = wn * 32 + (lane & 7);
        const int bh = (lane >> 3) & 1;

        uint32_t aH[4][4], aL[4][4];
#pragma unroll
        for (int mi = 0; mi < 4; ++mi) {
            const uint32_t off = swz(arow + mi * 16, s, ah);
            LDSM4(aH[mi][0], aH[mi][1], aH[mi][2], aH[mi][3], ah_t + off);
            LDSM4(aL[mi][0], aL[mi][1], aL[mi][2], aL[mi][3], al_t + off);
        }
        uint32_t bH[4][2], bL[4][2];
#pragma unroll
        for (int ni = 0; ni < 4; ++ni) {
            const uint32_t off = swz(brow + ni * 8, s, bh);
            LDSM2(bH[ni][0], bH[ni][1], bh_t + off);
            LDSM2(bL[ni][0], bL[ni][1], bl_t + off);
        }
#pragma unroll
        for (int mi = 0; mi < 4; ++mi)
#pragma unroll
            for (int ni = 0; ni < 4; ++ni) {
                MMA_BF16(acc[mi][ni], aH[mi][0], aH[mi][1], aH[mi][2], aH[mi][3],
                         bH[ni][0], bH[ni][1]);
                MMA_BF16(acc[mi][ni], aH[mi][0], aH[mi][1], aH[mi][2], aH[mi][3],
                         bL[ni][0], bL[ni][1]);
                MMA_BF16(acc[mi][ni], aL[mi][0], aL[mi][1], aL[mi][2], aL[mi][3],
                         bH[ni][0], bH[ni][1]);
            }
    };

    ldgsts(0, 0); CP_COMMIT();
    ldgsts(1, 1); CP_COMMIT();
    ldgsts(2, 2); CP_COMMIT();

    for (int ks = 0; ks < NST; ++ks) {
        CP_WAIT2();
        __syncthreads();
        if (ks + 3 < NST) ldgsts(ks + 3, (ks + 3) & 3);
        CP_COMMIT();
        const int buf = ks & 3;
        compute16(buf, 0);
        compute16(buf, 1);
    }

    float* Y = z ? g_y2 : g_y;
#pragma unroll
    for (int ni = 0; ni < 4; ++ni) {
        const int oc = o0 + wn * 32 + ni * 8 + 2 * tq;
        float2 bias = make_float2(0.f, 0.f);
        if (z == 0) bias = *(const float2*)(b1 + oc);
#pragma unroll
        for (int mi = 0; mi < 4; ++mi) {
            const int crow = c0 + wm * 64 + mi * 16 + g;
            float2 v0 = make_float2(acc[mi][ni][0] + bias.x, acc[mi][ni][1] + bias.y);
            float2 v1 = make_float2(acc[mi][ni][2] + bias.x, acc[mi][ni][3] + bias.y);
            *(float2*)(Y + ((size_t)b * C2 + crow)     * OUTC + oc) = v0;
            *(float2*)(Y + ((size_t)b * C2 + crow + 8) * OUTC + oc) = v1;
        }
    }
}

// ---------------- statsepi: fold partials + BN stats, barrier, BN+ReLU+transpose --
// grid 128 blocks x 256 thr (all resident on 148 SMs -> spin barrier is safe)
__global__ __launch_bounds__(256) void statsepi_kernel(const float* __restrict__ gamma,
                                                       const float* __restrict__ beta,
                                                       float* __restrict__ out) {
    __shared__ float rs[256], rq[256];
    __shared__ float tile[32][33];
    const int t = threadIdx.x;

    // ---- phase 1: ysum + per-channel stats (2 channels per block) ----
    const int c = blockIdx.x * 2 + (t >> 7);
    const int l = t & 127;
    const int oq = l * 2;
    float s = 0.f, s2 = 0.f;
#pragma unroll
    for (int b = 0; b < BB; ++b) {
        size_t idx = ((size_t)b * C2 + c) * OUTC + oq;
        float2 v0 = *(const float2*)(g_y + idx);
        float2 v1 = *(const float2*)(g_y2 + idx);
        float2 v = make_float2(v0.x + v1.x, v0.y + v1.y);
        *(float2*)(g_ysum + idx) = v;
        s += v.x + v.y;
        s2 = fmaf(v.x, v.x, s2);
        s2 = fmaf(v.y, v.y, s2);
    }
    rs[t] = s; rq[t] = s2;
    __syncthreads();
    for (int st = 64; st > 0; st >>= 1) {
        if (l < st) { rs[t] += rs[t + st]; rq[t] += rq[t + st]; }
        __syncthreads();
    }
    if (l == 0) {
        float mean = rs[t] * (1.f / 4096.f);
        float var  = rq[t] * (1.f / 4096.f) - mean * mean;
        g_mean[c] = mean;
        g_rstd[c] = rsqrtf(var + 1e-5f);
    }

    // ---- grid barrier (all 128 blocks resident) ----
    __syncthreads();
    if (t == 0) {
        __threadfence();
        atomicAdd(&g_ctr, 1);
        while (atomicAdd(&g_ctr, 0) < 128) { }
        __threadfence();
    }
    __syncthreads();

    // ---- phase 2: BN apply + ReLU + transpose (8 tiles of 32x32 per block) ----
    const int tx = t & 31, ty = t >> 5;
#pragma unroll
    for (int it = 0; it < 8; ++it) {
        const int tileid = blockIdx.x * 8 + it;
        const int b  = tileid >> 6;
        const int rm = tileid & 63;
        const int c0 = (rm & 7) * 32, o0 = (rm >> 3) * 32;
        __syncthreads();
#pragma unroll
        for (int i = 0; i < 4; ++i) {
            int cc = c0 + ty + i * 8;
            float v = g_ysum[((size_t)b * C2 + cc) * OUTC + o0 + tx];
            v = fmaf(gamma[cc] * g_rstd[cc], v - g_mean[cc], beta[cc]);
            tile[ty + i * 8][tx] = fmaxf(v, 0.f);
        }
        __syncthreads();
#pragma unroll
        for (int i = 0; i < 4; ++i) {
            int o = o0 + ty + i * 8;
            out[((size_t)b * OUTC + o) * C2 + c0 + tx] = tile[tx][ty + i * 8];
        }
    }
}

// ---------------- launch ----------------------------------------------------------
extern "C" void kernel_launch(void* const* d_in, const int* in_sizes, int n_in,
                              void* d_out, int out_size) {
    const float* x2    = (const float*)d_in[1];
    const float* xyz1  = (const float*)d_in[2];
    const float* xyz2  = (const float*)d_in[3];
    const float* W1    = (const float*)d_in[4];
    const float* b1    = (const float*)d_in[5];
    const float* gamma = (const float*)d_in[6];
    const float* beta  = (const float*)d_in[7];
    float* out = (float*)d_out;

    const int dyn_smem = 16 * GTILE;   // 128 KB
    cudaFuncSetAttribute(gemm_mma_kernel, cudaFuncAttributeMaxDynamicSharedMemorySize, dyn_smem);

    mega0_kernel<<<1344, 1024>>>(W1, x2, xyz1, xyz2);                    // idx 0
    fillk_kernel<<<dim3(4, BB), 1024>>>();                               // idx 1
    tbuild_kernel<<<dim3(N2 / 4, BB), 256>>>();                          // idx 2
    bpack_kernel<<<dim3(32, 8, BB), dim3(32, 8)>>>();                    // idx 3 <- profiled
    gemm_mma_kernel<<<dim3(8, BB), 256, dyn_smem>>>(b1);                 // idx 4
    statsepi_kernel<<<128, 256>>>(gamma, beta, out);                     // idx 5
}

// round 14
// speedup vs baseline: 1.1315x; 1.1315x over previous
#include <cuda_runtime.h>
#include <cstdint>

#define BB   16
#define N1   4096
#define N2   1024
#define C2   256
#define OUTC 256
#define KG   4096
#define NNZ  (N1 * 3)

// ---------------- scratch ------------------------------------------------------
__device__ float4         g_wi[BB * N1];
__device__ int            g_histq[BB][4][N2];
__device__ int            g_off[BB * N2];
__device__ int            g_end[BB * N2];
__device__ float2         g_le[BB * NNZ];
__device__ float          g_W1T[(size_t)KG * OUTC];
__device__ unsigned short g_APh[(size_t)BB * C2 * N2];    // A: bf16 hi plane [b][c][k]
__device__ unsigned short g_APl[(size_t)BB * C2 * N2];
__device__ unsigned short g_BPh[(size_t)BB * N2 * OUTC];  // B: bf16 hi plane [b][m][o]
__device__ unsigned short g_BPl[(size_t)BB * N2 * OUTC];
__device__ float          g_y[BB * C2 * OUTC];
__device__ float          g_y2[BB * C2 * OUTC];
__device__ float          g_ysum[BB * C2 * OUTC];
__device__ float          g_mean[C2];
__device__ float          g_rstd[C2];

__device__ __forceinline__ uint32_t smem_u32(const void* p) {
    uint32_t a;
    asm("{ .reg .u64 t; cvta.to.shared.u64 t, %1; cvt.u32.u64 %0, t; }" : "=r"(a) : "l"(p));
    return a;
}
__device__ __forceinline__ void split2(float f0, float f1, uint32_t& h, uint32_t& l) {
    asm("cvt.rn.bf16x2.f32 %0, %1, %2;" : "=r"(h) : "f"(f1), "f"(f0));
    float fh0 = __int_as_float(h << 16);
    float fh1 = __int_as_float(h & 0xffff0000u);
    asm("cvt.rn.bf16x2.f32 %0, %1, %2;" : "=r"(l) : "f"(f1 - fh1), "f"(f0 - fh0));
}
__device__ __forceinline__ void fma2(unsigned long long& d, unsigned long long a,
                                     unsigned long long b) {
    asm("fma.rn.f32x2 %0, %1, %2, %0;" : "+l"(d) : "l"(a), "l"(b));
}

// ---------------- kernel: 3-NN + weights (f32x2, 256-thread blocks) ---------------
__global__ __launch_bounds__(256) void knn_kernel(const float* __restrict__ xyz1,
                                                  const float* __restrict__ xyz2) {
    __shared__ float4 qA[512];
    __shared__ float4 qB[512];
    const int b = blockIdx.y;
    const float* x2b = xyz2 + (size_t)b * N2 * 3;
    for (int j = threadIdx.x; j < N2; j += blockDim.x) {
        float x = x2b[j * 3 + 0], y = x2b[j * 3 + 1], z = x2b[j * 3 + 2];
        int p = j >> 1, hi = j & 1;
        ((float*)&qA[p])[hi]     = x;
        ((float*)&qA[p])[2 + hi] = y;
        ((float*)&qB[p])[hi]     = z;
        ((float*)&qB[p])[2 + hi] = x * x + y * y + z * z;
    }
    __syncthreads();

    const int n = blockIdx.x * 256 + threadIdx.x;
    const float* p = xyz1 + ((size_t)b * N1 + n) * 3;
    const float px = p[0], py = p[1], pz = p[2];
    const float pp = px * px + py * py + pz * pz;
    unsigned long long ax2, ay2, az2;
    {
        float ax = -2.f * px, ay = -2.f * py, az = -2.f * pz;
        asm("mov.b64 %0, {%1,%1};" : "=l"(ax2) : "f"(ax));
        asm("mov.b64 %0, {%1,%1};" : "=l"(ay2) : "f"(ay));
        asm("mov.b64 %0, {%1,%1};" : "=l"(az2) : "f"(az));
    }
    const float INF = __int_as_float(0x7f800000);
    float s0 = INF, s1 = INF, s2 = INF;
    int i0 = 0, i1 = 0, i2 = 0;

#pragma unroll 4
    for (int q = 0; q < 512; ++q) {
        ulonglong2 A = *(const ulonglong2*)(qA + q);
        ulonglong2 B = *(const ulonglong2*)(qB + q);
        unsigned long long acc = B.y;
        fma2(acc, ax2, A.x);
        fma2(acc, ay2, A.y);
        fma2(acc, az2, B.x);
        float slo, shi;
        asm("mov.b64 {%0,%1}, %2;" : "=f"(slo), "=f"(shi) : "l"(acc));
#pragma unroll
        for (int h = 0; h < 2; ++h) {
            float s = h ? shi : slo;
            int j = 2 * q + h;
            if (s < s2) {
                if (s < s1) {
                    s2 = s1; i2 = i1;
                    if (s < s0) { s1 = s0; i1 = i0; s0 = s; i0 = j; }
                    else        { s1 = s;  i1 = j; }
                } else { s2 = s; i2 = j; }
            }
        }
    }
    float d0 = s0 + pp, d1 = s1 + pp, d2 = s2 + pp;
    float r0 = 1.f / (d0 + 1e-8f), r1 = 1.f / (d1 + 1e-8f), r2 = 1.f / (d2 + 1e-8f);
    float rs = 1.f / (r0 + r1 + r2);
    int packed = i0 | (i1 << 10) | (i2 << 20);
    g_wi[b * N1 + n] = make_float4(r0 * rs, r1 * rs, r2 * rs, __int_as_float(packed));
}

// ---------------- kernel: fused (W1 transpose) | (x2 pack) | (quarter hist) ------
__global__ __launch_bounds__(1024) void prep_kernel(const float* __restrict__ W1,
                                                    const float* __restrict__ x2) {
    __shared__ __align__(16) char smem[17408];
    const int t = threadIdx.x;

    if (blockIdx.x < 256) {
        float (*tile)[65] = (float (*)[65])smem;
        const int tt = blockIdx.x;
        const int n0 = (tt & 63) * 64, o0 = (tt >> 6) * 64;
        const int tx = t & 63, ty = t >> 6;
#pragma unroll
        for (int i = 0; i < 4; ++i)
            tile[ty + 16 * i][tx] = W1[(size_t)(o0 + ty + 16 * i) * KG + n0 + tx];
        __syncthreads();
#pragma unroll
        for (int i = 0; i < 4; ++i)
            g_W1T[(size_t)(n0 + ty + 16 * i) * OUTC + o0 + tx] = tile[tx][ty + 16 * i];
    } else if (blockIdx.x < 1280) {
        float (*tile)[65] = (float (*)[65])smem;
        const int tt = blockIdx.x - 256;
        const int b = tt >> 6;
        const int ti = tt & 63;
        const int k0 = (ti >> 2) * 64, c0 = (ti & 3) * 64;
        const int kr = t >> 4, c4 = (t & 15) * 4;
        float4 f4 = *(const float4*)(x2 + ((size_t)(b * N2 + k0 + kr)) * 256 + c0 + c4);
        tile[kr][c4 + 0] = f4.x; tile[kr][c4 + 1] = f4.y;
        tile[kr][c4 + 2] = f4.z; tile[kr][c4 + 3] = f4.w;
        __syncthreads();
        const int cr = t >> 4, k4 = (t & 15) * 4;
        float g0 = tile[k4 + 0][cr], g1 = tile[k4 + 1][cr];
        float g2 = tile[k4 + 2][cr], g3 = tile[k4 + 3][cr];
        uint32_t h01, l01, h23, l23;
        split2(g0, g1, h01, l01);
        split2(g2, g3, h23, l23);
        const size_t doff = ((size_t)(b * 256 + c0 + cr) << 10) + k0 + k4;
        *(uint2*)(g_APh + doff) = make_uint2(h01, h23);
        *(uint2*)(g_APl + doff) = make_uint2(l01, l23);
    } else {
        int* hist = (int*)smem;
        const int tt = blockIdx.x - 1280;      // 0..63
        const int b = tt >> 2, qq = tt & 3;
        hist[t] = 0;
        __syncthreads();
        const int n = qq * 1024 + t;
        int p = __float_as_int(g_wi[b * N1 + n].w);
        atomicAdd(&hist[p & 1023], 1);
        atomicAdd(&hist[(p >> 10) & 1023], 1);
        atomicAdd(&hist[(p >> 20) & 1023], 1);
        __syncthreads();
        g_histq[b][qq][t] = hist[t];
    }
}

// ---------------- kernel: per-quarter scan + CSC fill (128 blocks) ---------------
__global__ __launch_bounds__(1024) void fillk_kernel() {
    __shared__ int cur[N2];
    __shared__ int wpart[32];
    const int b = blockIdx.y, qq = blockIdx.x, t = threadIdx.x;
    const int m = t;
    const int h0 = g_histq[b][0][m], h1 = g_histq[b][1][m];
    const int h2 = g_histq[b][2][m], h3 = g_histq[b][3][m];
    const int cnt = h0 + h1 + h2 + h3;
    int before = 0;
    if (qq > 0) before += h0;
    if (qq > 1) before += h1;
    if (qq > 2) before += h2;

    const int lane = t & 31, wid = t >> 5;
    int v = cnt;
#pragma unroll
    for (int d = 1; d < 32; d <<= 1) {
        int u = __shfl_up_sync(0xffffffffu, v, d);
        if (lane >= d) v += u;
    }
    if (lane == 31) wpart[wid] = v;
    __syncthreads();
    if (wid == 0) {
        int w = wpart[lane];
#pragma unroll
        for (int d = 1; d < 32; d <<= 1) {
            int u = __shfl_up_sync(0xffffffffu, w, d);
            if (lane >= d) w += u;
        }
        wpart[lane] = w;
    }
    __syncthreads();
    const int excl = v - cnt + (wid > 0 ? wpart[wid - 1] : 0);
    if (qq == 0) {
        g_off[b * N2 + m] = excl;
        g_end[b * N2 + m] = excl + cnt;
    }
    cur[m] = excl + before;
    __syncthreads();

    const int n = qq * 1024 + t;
    float4 wi = g_wi[b * N1 + n];
    int p = __float_as_int(wi.w);
    float fn = __int_as_float(n);
    const int lbase = b * NNZ;
    int p0 = atomicAdd(&cur[p & 1023], 1);
    g_le[lbase + p0] = make_float2(wi.x, fn);
    int p1 = atomicAdd(&cur[(p >> 10) & 1023], 1);
    g_le[lbase + p1] = make_float2(wi.y, fn);
    int p2 = atomicAdd(&cur[(p >> 20) & 1023], 1);
    g_le[lbase + p2] = make_float2(wi.z, fn);
}

// ---------------- kernel (PROFILED): build T -> B planes directly [b][m][o] ------
__global__ __launch_bounds__(256) void tbuild_kernel() {
    const int b = blockIdx.y;
    const int m = blockIdx.x * 4 + (threadIdx.x >> 6);
    const int o4 = (threadIdx.x & 63) << 2;
    const int lbase = b * NNZ;
    const int s0 = __ldg(&g_off[b * N2 + m]);
    const int s1 = __ldg(&g_end[b * N2 + m]);

    float4 acc = make_float4(0.f, 0.f, 0.f, 0.f);
    int i = s0;
    for (; i + 2 <= s1; i += 2) {
        float2 e0 = __ldg(&g_le[lbase + i]);
        float2 e1 = __ldg(&g_le[lbase + i + 1]);
        int n0 = __float_as_int(e0.y), n1 = __float_as_int(e1.y);
        float4 v0 = *(const float4*)(g_W1T + ((size_t)n0 << 8) + o4);
        float4 v1 = *(const float4*)(g_W1T + ((size_t)n1 << 8) + o4);
        acc.x = fmaf(e0.x, v0.x, acc.x); acc.y = fmaf(e0.x, v0.y, acc.y);
        acc.z = fmaf(e0.x, v0.z, acc.z); acc.w = fmaf(e0.x, v0.w, acc.w);
        acc.x = fmaf(e1.x, v1.x, acc.x); acc.y = fmaf(e1.x, v1.y, acc.y);
        acc.z = fmaf(e1.x, v1.z, acc.z); acc.w = fmaf(e1.x, v1.w, acc.w);
    }
    if (i < s1) {
        float2 e = __ldg(&g_le[lbase + i]);
        int n = __float_as_int(e.y);
        float4 v = *(const float4*)(g_W1T + ((size_t)n << 8) + o4);
        acc.x = fmaf(e.x, v.x, acc.x); acc.y = fmaf(e.x, v.y, acc.y);
        acc.z = fmaf(e.x, v.z, acc.z); acc.w = fmaf(e.x, v.w, acc.w);
    }
    uint32_t h01, l01, h23, l23;
    split2(acc.x, acc.y, h01, l01);
    split2(acc.z, acc.w, h23, l23);
    const size_t idx = ((size_t)(b * N2 + m) << 8) + o4;
    *(uint2*)(g_BPh + idx) = make_uint2(h01, h23);
    *(uint2*)(g_BPl + idx) = make_uint2(l01, l23);
}

// ---------------- GEMM: cp.async 4-stage, B via ldmatrix.trans -------------------
#define GTILE 8192
#define NST   16               // 512 / 32 per split

#define MMA_BF16(d, A0, A1, A2, A3, B0, B1)                                     \
    asm volatile("mma.sync.aligned.m16n8k16.row.col.f32.bf16.bf16.f32 "         \
        "{%0,%1,%2,%3}, {%4,%5,%6,%7}, {%8,%9}, {%0,%1,%2,%3};"                 \
        : "+f"((d)[0]), "+f"((d)[1]), "+f"((d)[2]), "+f"((d)[3])                \
        : "r"(A0), "r"(A1), "r"(A2), "r"(A3), "r"(B0), "r"(B1))

#define LDSM4(r0, r1, r2, r3, a)                                                \
    asm volatile("ldmatrix.sync.aligned.m8n8.x4.shared.b16 {%0,%1,%2,%3}, [%4];" \
        : "=r"(r0), "=r"(r1), "=r"(r2), "=r"(r3) : "r"(a))

#define LDSM2T(r0, r1, a)                                                       \
    asm volatile("ldmatrix.sync.aligned.m8n8.x2.trans.shared.b16 {%0,%1}, [%2];" \
        : "=r"(r0), "=r"(r1) : "r"(a))

#define CP_ASYNC(dst, src)                                                      \
    asm volatile("cp.async.cg.shared.global [%0], [%1], 16;"                    \
        :: "r"(dst), "l"(src) : "memory")
#define CP_COMMIT() asm volatile("cp.async.commit_group;" ::: "memory")
#define CP_WAIT2()  asm volatile("cp.async.wait_group 2;" ::: "memory")

// A-tile swizzle (rows = c, 64B): row r, k16 subtile s, 16B half h
__device__ __forceinline__ uint32_t swz(int r, int s, int h) {
    return (uint32_t)(r * 64 + ((s ^ ((r >> 1) & 1)) << 5) + ((h ^ ((r >> 2) & 1)) << 4));
}
// B-tile swizzle (rows = m, 256B = 16 chunks of 16B): chunk XOR row
__device__ __forceinline__ uint32_t bswz(int m, int ch) {
    return (uint32_t)(m * 256 + ((ch ^ (m & 15)) << 4));
}

__global__ __launch_bounds__(256, 1) void gemm_mma_kernel(const float* __restrict__ b1) {
    extern __shared__ __align__(128) char dyn[];
    const uint32_t sb = smem_u32(dyn);

    const int b  = blockIdx.y;
    const int c0 = (blockIdx.x & 1) * 128;
    const int o0 = ((blockIdx.x >> 1) & 1) * 128;
    const int z  = blockIdx.x >> 2;
    const int kbase = z * 512;

    const int tid  = threadIdx.x;
    const int lane = tid & 31;
    const int wid  = tid >> 5;
    const int wm   = wid & 1;
    const int wn   = wid >> 1;
    const int g    = lane >> 2;
    const int tq   = lane & 3;

    const unsigned short* aSrc[2] = {
        g_APh + ((size_t)(b * 256 + c0) << 10),
        g_APl + ((size_t)(b * 256 + c0) << 10)
    };
    const unsigned short* bSrc[2] = {
        g_BPh + (size_t)b * N2 * 256 + o0,
        g_BPl + (size_t)b * N2 * 256 + o0
    };

    float acc[4][4][4];
#pragma unroll
    for (int mi = 0; mi < 4; ++mi)
#pragma unroll
        for (int ni = 0; ni < 4; ++ni)
#pragma unroll
            for (int r = 0; r < 4; ++r) acc[mi][ni][r] = 0.f;

    auto ldgsts = [&](int ks, int buf) {
        const int kg = kbase + ks * 32;
        // A planes: 128 rows x 4 chunks each
#pragma unroll
        for (int pl = 0; pl < 2; ++pl) {
            const uint32_t tb = sb + (uint32_t)(buf * 4 + pl) * GTILE;
#pragma unroll
            for (int it = 0; it < 2; ++it) {
                const int cid = it * 256 + tid;
                const int r = cid >> 2, ch = cid & 3;
                const unsigned short* gp = aSrc[pl] + ((size_t)r << 10) + kg + ch * 8;
                CP_ASYNC(tb + swz(r, ch >> 1, ch & 1), gp);
            }
        }
        // B planes: 32 rows (m) x 16 chunks each
#pragma unroll
        for (int pl = 0; pl < 2; ++pl) {
            const uint32_t tb = sb + (uint32_t)(buf * 4 + 2 + pl) * GTILE;
#pragma unroll
            for (int it = 0; it < 2; ++it) {
                const int cid = it * 256 + tid;
                const int r = cid >> 4, ch = cid & 15;
                const unsigned short* gp = bSrc[pl] + ((size_t)(kg + r) << 8) + ch * 8;
                CP_ASYNC(tb + bswz(r, ch), gp);
            }
        }
    };

    auto compute16 = [&](int buf, int s) {
        const uint32_t ah_t = sb + (uint32_t)(buf * 4 + 0) * GTILE;
        const uint32_t al_t = sb + (uint32_t)(buf * 4 + 1) * GTILE;
        const uint32_t bh_t = sb + (uint32_t)(buf * 4 + 2) * GTILE;
        const uint32_t bl_t = sb + (uint32_t)(buf * 4 + 3) * GTILE;
        const int arow = wm * 64 + (lane & 15);
        const int ah = lane >> 4;
        const int bm  = s * 16 + (lane & 15);   // k-row for ldmatrix.trans (lanes 0-15)

        uint32_t aH[4][4], aL[4][4];
#pragma unroll
        for (int mi = 0; mi < 4; ++mi) {
            const uint32_t off = swz(arow + mi * 16, s, ah);
            LDSM4(aH[mi][0], aH[mi][1], aH[mi][2], aH[mi][3], ah_t + off);
            LDSM4(aL[mi][0], aL[mi][1], aL[mi][2], aL[mi][3], al_t + off);
        }
        uint32_t bH[4][2], bL[4][2];
#pragma unroll
        for (int ni = 0; ni < 4; ++ni) {
            const uint32_t off = bswz(bm, (wn * 32 + ni * 8) >> 3);
            LDSM2T(bH[ni][0], bH[ni][1], bh_t + off);
            LDSM2T(bL[ni][0], bL[ni][1], bl_t + off);
        }
#pragma unroll
        for (int mi = 0; mi < 4; ++mi)
#pragma unroll
            for (int ni = 0; ni < 4; ++ni) {
                MMA_BF16(acc[mi][ni], aH[mi][0], aH[mi][1], aH[mi][2], aH[mi][3],
                         bH[ni][0], bH[ni][1]);
                MMA_BF16(acc[mi][ni], aH[mi][0], aH[mi][1], aH[mi][2], aH[mi][3],
                         bL[ni][0], bL[ni][1]);
                MMA_BF16(acc[mi][ni], aL[mi][0], aL[mi][1], aL[mi][2], aL[mi][3],
                         bH[ni][0], bH[ni][1]);
            }
    };

    ldgsts(0, 0); CP_COMMIT();
    ldgsts(1, 1); CP_COMMIT();
    ldgsts(2, 2); CP_COMMIT();

    for (int ks = 0; ks < NST; ++ks) {
        CP_WAIT2();
        __syncthreads();
        if (ks + 3 < NST) ldgsts(ks + 3, (ks + 3) & 3);
        CP_COMMIT();
        const int buf = ks & 3;
        compute16(buf, 0);
        compute16(buf, 1);
    }

    float* Y = z ? g_y2 : g_y;
#pragma unroll
    for (int ni = 0; ni < 4; ++ni) {
        const int oc = o0 + wn * 32 + ni * 8 + 2 * tq;
        float2 bias = make_float2(0.f, 0.f);
        if (z == 0) bias = *(const float2*)(b1 + oc);
#pragma unroll
        for (int mi = 0; mi < 4; ++mi) {
            const int crow = c0 + wm * 64 + mi * 16 + g;
            float2 v0 = make_float2(acc[mi][ni][0] + bias.x, acc[mi][ni][1] + bias.y);
            float2 v1 = make_float2(acc[mi][ni][2] + bias.x, acc[mi][ni][3] + bias.y);
            *(float2*)(Y + ((size_t)b * C2 + crow)     * OUTC + oc) = v0;
            *(float2*)(Y + ((size_t)b * C2 + crow + 8) * OUTC + oc) = v1;
        }
    }
}

// ---------------- BN stats: fold 2 partials, write g_ysum -------------------------
__global__ __launch_bounds__(256) void stats_kernel() {
    const int t = threadIdx.x;
    const int c = blockIdx.x * 4 + (t >> 6);
    const int oq = (t & 63) * 4;
    float s = 0.f, s2 = 0.f;
#pragma unroll
    for (int b = 0; b < BB; ++b) {
        size_t idx = ((size_t)b * C2 + c) * OUTC + oq;
        float4 v0 = *(const float4*)(g_y + idx);
        float4 v1 = *(const float4*)(g_y2 + idx);
        float4 v;
        v.x = v0.x + v1.x; v.y = v0.y + v1.y;
        v.z = v0.z + v1.z; v.w = v0.w + v1.w;
        *(float4*)(g_ysum + idx) = v;
        s += (v.x + v.y) + (v.z + v.w);
        s2 = fmaf(v.x, v.x, s2); s2 = fmaf(v.y, v.y, s2);
        s2 = fmaf(v.z, v.z, s2); s2 = fmaf(v.w, v.w, s2);
    }
    __shared__ float rs[256], rq[256];
    rs[t] = s; rq[t] = s2;
    __syncthreads();
    for (int st = 32; st > 0; st >>= 1) {
        if ((t & 63) < st) { rs[t] += rs[t + st]; rq[t] += rq[t + st]; }
        __syncthreads();
    }
    if ((t & 63) == 0) {
        float mean = rs[t] * (1.f / 4096.f);
        float var  = rq[t] * (1.f / 4096.f) - mean * mean;
        g_mean[c] = mean;
        g_rstd[c] = rsqrtf(var + 1e-5f);
    }
}

// ---------------- BN apply + ReLU + transpose ------------------------------------
__global__ void epilogue_kernel(const float* __restrict__ gamma,
                                const float* __restrict__ beta,
                                float* __restrict__ out) {
    __shared__ float tile[32][33];
    const int b = blockIdx.z, c0 = blockIdx.x * 32, o0 = blockIdx.y * 32;
    const int tx = threadIdx.x, ty = threadIdx.y;
#pragma unroll
    for (int i = 0; i < 4; ++i) {
        int c = c0 + ty + i * 8;
        float v = g_ysum[((size_t)b * C2 + c) * OUTC + o0 + tx];
        v = fmaf(gamma[c] * g_rstd[c], v - g_mean[c], beta[c]);
        tile[ty + i * 8][tx] = fmaxf(v, 0.f);
    }
    __syncthreads();
#pragma unroll
    for (int i = 0; i < 4; ++i) {
        int o = o0 + ty + i * 8;
        out[((size_t)b * OUTC + o) * C2 + c0 + tx] = tile[tx][ty + i * 8];
    }
}

// ---------------- launch ----------------------------------------------------------
extern "C" void kernel_launch(void* const* d_in, const int* in_sizes, int n_in,
                              void* d_out, int out_size) {
    const float* x2    = (const float*)d_in[1];
    const float* xyz1  = (const float*)d_in[2];
    const float* xyz2  = (const float*)d_in[3];
    const float* W1    = (const float*)d_in[4];
    const float* b1    = (const float*)d_in[5];
    const float* gamma = (const float*)d_in[6];
    const float* beta  = (const float*)d_in[7];
    float* out = (float*)d_out;

    const int dyn_smem = 16 * GTILE;   // 128 KB (4 stages x 4 planes)
    cudaFuncSetAttribute(gemm_mma_kernel, cudaFuncAttributeMaxDynamicSharedMemorySize, dyn_smem);

    knn_kernel<<<dim3(N1 / 256, BB), 256>>>(xyz1, xyz2);                 // idx 0
    prep_kernel<<<256 + 1024 + 64, 1024>>>(W1, x2);                      // idx 1
    fillk_kernel<<<dim3(4, BB), 1024>>>();                               // idx 2
    tbuild_kernel<<<dim3(N2 / 4, BB), 256>>>();                          // idx 3 <- profiled
    gemm_mma_kernel<<<dim3(8, BB), 256, dyn_smem>>>(b1);                 // idx 4
    stats_kernel<<<C2 / 4, 256>>>();                                     // idx 5
    epilogue_kernel<<<dim3(8, 8, BB), dim3(32, 8)>>>(gamma, beta, out);  // idx 6
}